// round 16
// baseline (speedup 1.0000x reference)
#include <cuda_runtime.h>
#include <cuda_bf16.h>

#define NN   8192
#define INF  512
#define OUTF 128

typedef unsigned long long u64;

// ---------------- scratch (device globals; no allocations allowed) ----------
__device__ float g_ham[INF * OUTF];       // quaternion-expanded weight 512x128
__device__ float g_h[NN * OUTF];          // h = input @ hamilton
__device__ float g_s1[NN];
__device__ float g_s2[NN];
__device__ float g_hpp[2][NN * OUTF];     // unnormalized partial h_prime (per j-half)
__device__ float g_l[2][NN];              // partial softmax denominators
__device__ float g_hp[NN * OUTF];         // h_prime (pre-BN)
__device__ float g_part[2 * 64 * OUTF];   // BN partial sums / sumsq
__device__ float g_mean[OUTF];
__device__ float g_rstd[OUTF];

// ---------------- f32x2 helpers (Blackwell packed fp32) ---------------------
__device__ __forceinline__ u64 pack2(float x, float y) {
    u64 r;
    asm("mov.b64 %0, {%1, %2};" : "=l"(r) : "f"(x), "f"(y));
    return r;
}
__device__ __forceinline__ void unpack2(u64 v, float& x, float& y) {
    asm("mov.b64 {%0, %1}, %2;" : "=f"(x), "=f"(y) : "l"(v));
}
__device__ __forceinline__ u64 fma2(u64 a, u64 b, u64 c) {
    u64 d;
    asm("fma.rn.f32x2 %0, %1, %2, %3;" : "=l"(d) : "l"(a), "l"(b), "l"(c));
    return d;
}

// ---------------- K0: hamilton = make_quaternion_mul(W) ---------------------
__global__ void k_ham(const float* __restrict__ W) {
    int col = threadIdx.x;          // 0..127
    int row = blockIdx.x;           // 0..511
    int p  = row >> 7, rr = row & 127;
    int bc = col >> 5, cc = col & 31;
    const int   qt[4][4] = {{0,1,2,3},{1,0,3,2},{2,3,0,1},{3,2,1,0}};
    const float st[4][4] = {{1.f,-1.f,-1.f,-1.f},
                            {1.f, 1.f,-1.f, 1.f},
                            {1.f, 1.f, 1.f,-1.f},
                            {1.f,-1.f, 1.f, 1.f}};
    g_ham[row * OUTF + col] = st[bc][p] * W[rr * OUTF + qt[bc][p] * 32 + cc];
}

// ---------------- K1: h = input @ hamilton  (8192x512 @ 512x128) ------------
__global__ __launch_bounds__(256) void k_h(const float* __restrict__ inp) {
    __shared__ u64   A2[64][32];     // input tile, value duplicated into both halves
    __shared__ float Bs[32][64];     // hamilton tile
    int tid = threadIdx.x;
    int tx = tid & 31, ty = tid >> 5;
    int i0 = blockIdx.y * 64, f0 = blockIdx.x * 64;

    u64 acc[8];
#pragma unroll
    for (int r = 0; r < 8; r++) acc[r] = 0ULL;

    for (int kt = 0; kt < INF / 32; kt++) {
        int k0 = kt * 32;
        __syncthreads();
#pragma unroll
        for (int q = 0; q < 8; q++) {
            int p = tid + 256 * q;
            int r = p >> 5, c = p & 31;
            float v = inp[(size_t)(i0 + r) * INF + k0 + c];
            A2[r][c] = pack2(v, v);
        }
#pragma unroll
        for (int q = 0; q < 8; q++) {
            int p = tid + 256 * q;
            int r = p >> 6, c = p & 63;
            Bs[r][c] = g_ham[(k0 + r) * OUTF + f0 + c];
        }
        __syncthreads();
#pragma unroll 8
        for (int kk = 0; kk < 32; kk++) {
            u64 b = *(const u64*)&Bs[kk][2 * tx];
#pragma unroll
            for (int rr = 0; rr < 8; rr++)
                acc[rr] = fma2(A2[ty + 8 * rr][kk], b, acc[rr]);
        }
    }
#pragma unroll
    for (int rr = 0; rr < 8; rr++) {
        float x, y;
        unpack2(acc[rr], x, y);
        int row = i0 + ty + 8 * rr;
        float2 o = make_float2(x, y);
        *(float2*)&g_h[(size_t)row * OUTF + f0 + 2 * tx] = o;
    }
}

// ---------------- K2: s1 = h@a[:128], s2 = h@a[128:] ------------------------
__global__ __launch_bounds__(256) void k_s(const float* __restrict__ a) {
    int lane = threadIdx.x & 31, w = threadIdx.x >> 5;
    int row = blockIdx.x * 8 + w;
    float s1 = 0.f, s2 = 0.f;
#pragma unroll
    for (int q = 0; q < 4; q++) {
        int f = lane + 32 * q;
        float hv = g_h[(size_t)row * OUTF + f];
        s1 += hv * a[f];
        s2 += hv * a[OUTF + f];
    }
#pragma unroll
    for (int m = 16; m > 0; m >>= 1) {
        s1 += __shfl_xor_sync(0xffffffffu, s1, m);
        s2 += __shfl_xor_sync(0xffffffffu, s2, m);
    }
    if (lane == 0) { g_s1[row] = s1; g_s2[row] = s2; }
}

// ---------------- K3: fused masked-softmax @ h (split over 2 j-halves) ------
// CTA = 64 rows x 4096 j, 128 threads. Thread tile: 8 rows (ty+8rr) x 8 cols
// (4tx.., 64+4tx..). Ws stored PLAIN (no duplication, 8 KB); (w,w) packs are
// built in registers (ALU movs) — halves Ws crossbar wavefronts. Hs reads
// amortize over 8 rows. Per 2-j step: 32 smem wavefronts vs 64 fma2 -> 1:1
// crossbar:fma balance (was 2:1).
// Single pass over j (no max-subtract: exp args bounded ~[-5,+12]; masked
// entries contribute exactly 0).
__global__ __launch_bounds__(128, 4) void k_attn(const int* __restrict__ adj) {
    __shared__ float Ws[64][32];       // 8 KB, plain weights
    __shared__ float Hs[32][OUTF];     // 16 KB
    __shared__ float l_s[64];

    int tid = threadIdx.x;
    int tx = tid & 15, ty = tid >> 4;  // tx: f-group (8 cols), ty: row base (0..7)
    int half = blockIdx.x;             // 0 or 1: j-half
    int i0 = blockIdx.y * 64;
    int jbase = half * (NN / 2);

    // w-build mapping: 4 rows per thread (r_w + 16k), 4 cols c0..c0+3
    int r_w = tid >> 3;                // 0..15
    int c0  = (tid & 7) << 2;
    float s1v0 = g_s1[i0 + r_w];
    float s1v1 = g_s1[i0 + r_w + 16];
    float s1v2 = g_s1[i0 + r_w + 32];
    float s1v3 = g_s1[i0 + r_w + 48];

    u64 acc[8][4];                     // [row rr][lo.x lo.y hi.x hi.y]
#pragma unroll
    for (int r = 0; r < 8; r++)
#pragma unroll
        for (int c = 0; c < 4; c++) acc[r][c] = 0ULL;
    float lp0 = 0.f, lp1 = 0.f, lp2 = 0.f, lp3 = 0.f;

    const int NT = (NN / 2) / 32;      // 128 tiles per half
    for (int t = 0; t < NT; t++) {
        int j0 = jbase + 32 * t;
        __syncthreads();               // previous tile's accumulate done

        // ---- build w tile (mask + leakyrelu + exp), store PLAIN ----
        float4 s2v = *(const float4*)&g_s2[j0 + c0];
        {
            int4 av = *(const int4*)&adj[(size_t)(i0 + r_w) * NN + j0 + c0];
            float e, w0, w1, w2, w3;
            e = s1v0 + s2v.x; e = e > 0.f ? e : 0.2f * e; w0 = av.x > 0 ? __expf(e) : 0.f;
            e = s1v0 + s2v.y; e = e > 0.f ? e : 0.2f * e; w1 = av.y > 0 ? __expf(e) : 0.f;
            e = s1v0 + s2v.z; e = e > 0.f ? e : 0.2f * e; w2 = av.z > 0 ? __expf(e) : 0.f;
            e = s1v0 + s2v.w; e = e > 0.f ? e : 0.2f * e; w3 = av.w > 0 ? __expf(e) : 0.f;
            lp0 += (w0 + w1) + (w2 + w3);
            *(float4*)&Ws[r_w][c0] = make_float4(w0, w1, w2, w3);
        }
        {
            int4 av = *(const int4*)&adj[(size_t)(i0 + r_w + 16) * NN + j0 + c0];
            float e, w0, w1, w2, w3;
            e = s1v1 + s2v.x; e = e > 0.f ? e : 0.2f * e; w0 = av.x > 0 ? __expf(e) : 0.f;
            e = s1v1 + s2v.y; e = e > 0.f ? e : 0.2f * e; w1 = av.y > 0 ? __expf(e) : 0.f;
            e = s1v1 + s2v.z; e = e > 0.f ? e : 0.2f * e; w2 = av.z > 0 ? __expf(e) : 0.f;
            e = s1v1 + s2v.w; e = e > 0.f ? e : 0.2f * e; w3 = av.w > 0 ? __expf(e) : 0.f;
            lp1 += (w0 + w1) + (w2 + w3);
            *(float4*)&Ws[r_w + 16][c0] = make_float4(w0, w1, w2, w3);
        }
        {
            int4 av = *(const int4*)&adj[(size_t)(i0 + r_w + 32) * NN + j0 + c0];
            float e, w0, w1, w2, w3;
            e = s1v2 + s2v.x; e = e > 0.f ? e : 0.2f * e; w0 = av.x > 0 ? __expf(e) : 0.f;
            e = s1v2 + s2v.y; e = e > 0.f ? e : 0.2f * e; w1 = av.y > 0 ? __expf(e) : 0.f;
            e = s1v2 + s2v.z; e = e > 0.f ? e : 0.2f * e; w2 = av.z > 0 ? __expf(e) : 0.f;
            e = s1v2 + s2v.w; e = e > 0.f ? e : 0.2f * e; w3 = av.w > 0 ? __expf(e) : 0.f;
            lp2 += (w0 + w1) + (w2 + w3);
            *(float4*)&Ws[r_w + 32][c0] = make_float4(w0, w1, w2, w3);
        }
        {
            int4 av = *(const int4*)&adj[(size_t)(i0 + r_w + 48) * NN + j0 + c0];
            float e, w0, w1, w2, w3;
            e = s1v3 + s2v.x; e = e > 0.f ? e : 0.2f * e; w0 = av.x > 0 ? __expf(e) : 0.f;
            e = s1v3 + s2v.y; e = e > 0.f ? e : 0.2f * e; w1 = av.y > 0 ? __expf(e) : 0.f;
            e = s1v3 + s2v.z; e = e > 0.f ? e : 0.2f * e; w2 = av.z > 0 ? __expf(e) : 0.f;
            e = s1v3 + s2v.w; e = e > 0.f ? e : 0.2f * e; w3 = av.w > 0 ? __expf(e) : 0.f;
            lp3 += (w0 + w1) + (w2 + w3);
            *(float4*)&Ws[r_w + 48][c0] = make_float4(w0, w1, w2, w3);
        }

        // ---- stage h tile (32 rows x 128 f = 1024 float4 / 128 thr) ----
#pragma unroll
        for (int q = 0; q < 8; q++) {
            int p = tid + 128 * q;
            int hr = p >> 5, hc = (p & 31) << 2;
            *(float4*)&Hs[hr][hc] = *(const float4*)&g_h[(size_t)(j0 + hr) * OUTF + hc];
        }
        __syncthreads();

        // ---- accumulate: per 2-j: 4 LDS.128 + 8 LDS.64 (32 wf) / 64 fma2 ----
#pragma unroll 2
        for (int jp = 0; jp < 16; jp++) {
            int jj = 2 * jp;
            ulonglong2 h0a = *(const ulonglong2*)&Hs[jj][4 * tx];
            ulonglong2 h0b = *(const ulonglong2*)&Hs[jj][64 + 4 * tx];
            ulonglong2 h1a = *(const ulonglong2*)&Hs[jj + 1][4 * tx];
            ulonglong2 h1b = *(const ulonglong2*)&Hs[jj + 1][64 + 4 * tx];
#pragma unroll
            for (int rr = 0; rr < 8; rr++) {
                float2 wv = *(const float2*)&Ws[ty + 8 * rr][jj];
                u64 w0 = pack2(wv.x, wv.x);
                u64 w1 = pack2(wv.y, wv.y);
                acc[rr][0] = fma2(w0, h0a.x, acc[rr][0]);
                acc[rr][1] = fma2(w0, h0a.y, acc[rr][1]);
                acc[rr][2] = fma2(w0, h0b.x, acc[rr][2]);
                acc[rr][3] = fma2(w0, h0b.y, acc[rr][3]);
                acc[rr][0] = fma2(w1, h1a.x, acc[rr][0]);
                acc[rr][1] = fma2(w1, h1a.y, acc[rr][1]);
                acc[rr][2] = fma2(w1, h1b.x, acc[rr][2]);
                acc[rr][3] = fma2(w1, h1b.y, acc[rr][3]);
            }
        }
    }

    // ---- finalize: partial row sums (reduce over 8 col-threads) ----
#pragma unroll
    for (int m = 1; m < 8; m <<= 1) {
        lp0 += __shfl_xor_sync(0xffffffffu, lp0, m);
        lp1 += __shfl_xor_sync(0xffffffffu, lp1, m);
        lp2 += __shfl_xor_sync(0xffffffffu, lp2, m);
        lp3 += __shfl_xor_sync(0xffffffffu, lp3, m);
    }
    __syncthreads();
    if ((tid & 7) == 0) {
        l_s[r_w]      = lp0;
        l_s[r_w + 16] = lp1;
        l_s[r_w + 32] = lp2;
        l_s[r_w + 48] = lp3;
    }
    __syncthreads();
    if (tid < 64) g_l[half][i0 + tid] = l_s[tid];

    // ---- write unnormalized partial acc ----
#pragma unroll
    for (int rr = 0; rr < 8; rr++) {
        int row = ty + 8 * rr;
        float x0, x1, x2, x3;
        unpack2(acc[rr][0], x0, x1);
        unpack2(acc[rr][1], x2, x3);
        *(float4*)&g_hpp[half][(size_t)(i0 + row) * OUTF + 4 * tx] =
            make_float4(x0, x1, x2, x3);
        unpack2(acc[rr][2], x0, x1);
        unpack2(acc[rr][3], x2, x3);
        *(float4*)&g_hpp[half][(size_t)(i0 + row) * OUTF + 64 + 4 * tx] =
            make_float4(x0, x1, x2, x3);
    }
}

// ---------------- K3b: combine j-halves: hp = (p0+p1)/(l0+l1) ---------------
__global__ __launch_bounds__(256) void k_comb() {
    int idx = blockIdx.x * 256 + threadIdx.x;       // over NN*OUTF
    int row = idx >> 7;
    float inv = 1.0f / (g_l[0][row] + g_l[1][row]);
    g_hp[idx] = (g_hpp[0][idx] + g_hpp[1][idx]) * inv;
}

// ---------------- K4/K5: BatchNorm stats (deterministic tree) ---------------
__global__ __launch_bounds__(256) void k_bn1() {
    int f = threadIdx.x & 127, half = threadIdx.x >> 7;
    int b = blockIdx.x;
    float s = 0.f, q = 0.f;
    for (int k = 0; k < 64; k++) {
        float v = g_hp[(size_t)(b * 128 + half + 2 * k) * OUTF + f];
        s += v; q += v * v;
    }
    __shared__ float ss[2][128], qs[2][128];
    ss[half][f] = s; qs[half][f] = q;
    __syncthreads();
    if (threadIdx.x < 128) {
        g_part[b * OUTF + f]              = ss[0][f] + ss[1][f];
        g_part[64 * OUTF + b * OUTF + f]  = qs[0][f] + qs[1][f];
    }
}

__global__ void k_bn2() {
    int f = threadIdx.x;  // 128 threads
    float S = 0.f, Q = 0.f;
    for (int b = 0; b < 64; b++) {
        S += g_part[b * OUTF + f];
        Q += g_part[64 * OUTF + b * OUTF + f];
    }
    float mean = S * (1.0f / NN);
    float var  = Q * (1.0f / NN) - mean * mean;
    g_mean[f] = mean;
    g_rstd[f] = rsqrtf(var + 1e-5f);
}

// ---------------- K6: normalize + ELU ---------------------------------------
__global__ __launch_bounds__(256) void k_out(const float* __restrict__ gamma,
                                             const float* __restrict__ beta,
                                             float* __restrict__ out) {
    int idx = blockIdx.x * 256 + threadIdx.x;
    int f = idx & 127;
    float v = (g_hp[idx] - g_mean[f]) * g_rstd[f] * gamma[f] + beta[f];
    out[idx] = v > 0.f ? v : expm1f(v);
}

// ---------------- launch -----------------------------------------------------
extern "C" void kernel_launch(void* const* d_in, const int* in_sizes, int n_in,
                              void* d_out, int out_size) {
    const float* inp   = (const float*)d_in[0];   // 8192x512
    const int*   adj   = (const int*)d_in[1];     // 8192x8192
    const float* W     = (const float*)d_in[2];   // 128x128
    const float* a     = (const float*)d_in[3];   // 256
    const float* gamma = (const float*)d_in[4];   // 128
    const float* beta  = (const float*)d_in[5];   // 128
    float* out = (float*)d_out;                   // 8192x128

    k_ham <<<512, 128>>>(W);
    k_h   <<<dim3(2, 128), 256>>>(inp);
    k_s   <<<1024, 256>>>(a);
    k_attn<<<dim3(2, 128), 128>>>(adj);
    k_comb<<<4096, 256>>>();
    k_bn1 <<<64, 256>>>();
    k_bn2 <<<1, 128>>>();
    k_out <<<4096, 256>>>(gamma, beta, out);
}

// round 17
// speedup vs baseline: 1.9104x; 1.9104x over previous
#include <cuda_runtime.h>
#include <cuda_bf16.h>

#define NN   8192
#define INF  512
#define OUTF 128
#define NSPLIT 4

typedef unsigned long long u64;

// ---------------- scratch (device globals; no allocations allowed) ----------
__device__ float g_ham[INF * OUTF];          // quaternion-expanded weight 512x128
__device__ float g_h[NN * OUTF];             // h = input @ hamilton
__device__ float g_s1[NN];
__device__ float g_s2[NN];
__device__ float g_hpp[NSPLIT][NN * OUTF];   // unnormalized partial h_prime (per j-quarter)
__device__ float g_l[NSPLIT][NN];            // partial softmax denominators
__device__ float g_hp[NN * OUTF];            // h_prime (pre-BN)
__device__ float g_part[2 * 64 * OUTF];      // BN partial sums / sumsq
__device__ float g_mean[OUTF];
__device__ float g_rstd[OUTF];

// ---------------- f32x2 helpers (Blackwell packed fp32) ---------------------
__device__ __forceinline__ u64 pack2(float x, float y) {
    u64 r;
    asm("mov.b64 %0, {%1, %2};" : "=l"(r) : "f"(x), "f"(y));
    return r;
}
__device__ __forceinline__ void unpack2(u64 v, float& x, float& y) {
    asm("mov.b64 {%0, %1}, %2;" : "=f"(x), "=f"(y) : "l"(v));
}
__device__ __forceinline__ u64 fma2(u64 a, u64 b, u64 c) {
    u64 d;
    asm("fma.rn.f32x2 %0, %1, %2, %3;" : "=l"(d) : "l"(a), "l"(b), "l"(c));
    return d;
}

// ---------------- K0: hamilton = make_quaternion_mul(W) ---------------------
__global__ void k_ham(const float* __restrict__ W) {
    int col = threadIdx.x;          // 0..127
    int row = blockIdx.x;           // 0..511
    int p  = row >> 7, rr = row & 127;
    int bc = col >> 5, cc = col & 31;
    const int   qt[4][4] = {{0,1,2,3},{1,0,3,2},{2,3,0,1},{3,2,1,0}};
    const float st[4][4] = {{1.f,-1.f,-1.f,-1.f},
                            {1.f, 1.f,-1.f, 1.f},
                            {1.f, 1.f, 1.f,-1.f},
                            {1.f,-1.f, 1.f, 1.f}};
    g_ham[row * OUTF + col] = st[bc][p] * W[rr * OUTF + qt[bc][p] * 32 + cc];
}

// ---------------- K1: h = input @ hamilton  (8192x512 @ 512x128) ------------
__global__ __launch_bounds__(256) void k_h(const float* __restrict__ inp) {
    __shared__ u64   A2[64][32];     // input tile, value duplicated into both halves
    __shared__ float Bs[32][64];     // hamilton tile
    int tid = threadIdx.x;
    int tx = tid & 31, ty = tid >> 5;
    int i0 = blockIdx.y * 64, f0 = blockIdx.x * 64;

    u64 acc[8];
#pragma unroll
    for (int r = 0; r < 8; r++) acc[r] = 0ULL;

    for (int kt = 0; kt < INF / 32; kt++) {
        int k0 = kt * 32;
        __syncthreads();
#pragma unroll
        for (int q = 0; q < 8; q++) {
            int p = tid + 256 * q;
            int r = p >> 5, c = p & 31;
            float v = inp[(size_t)(i0 + r) * INF + k0 + c];
            A2[r][c] = pack2(v, v);
        }
#pragma unroll
        for (int q = 0; q < 8; q++) {
            int p = tid + 256 * q;
            int r = p >> 6, c = p & 63;
            Bs[r][c] = g_ham[(k0 + r) * OUTF + f0 + c];
        }
        __syncthreads();
#pragma unroll 8
        for (int kk = 0; kk < 32; kk++) {
            u64 b = *(const u64*)&Bs[kk][2 * tx];
#pragma unroll
            for (int rr = 0; rr < 8; rr++)
                acc[rr] = fma2(A2[ty + 8 * rr][kk], b, acc[rr]);
        }
    }
#pragma unroll
    for (int rr = 0; rr < 8; rr++) {
        float x, y;
        unpack2(acc[rr], x, y);
        int row = i0 + ty + 8 * rr;
        float2 o = make_float2(x, y);
        *(float2*)&g_h[(size_t)row * OUTF + f0 + 2 * tx] = o;
    }
}

// ---------------- K2: s1 = h@a[:128], s2 = h@a[128:] ------------------------
__global__ __launch_bounds__(256) void k_s(const float* __restrict__ a) {
    int lane = threadIdx.x & 31, w = threadIdx.x >> 5;
    int row = blockIdx.x * 8 + w;
    float s1 = 0.f, s2 = 0.f;
#pragma unroll
    for (int q = 0; q < 4; q++) {
        int f = lane + 32 * q;
        float hv = g_h[(size_t)row * OUTF + f];
        s1 += hv * a[f];
        s2 += hv * a[OUTF + f];
    }
#pragma unroll
    for (int m = 16; m > 0; m >>= 1) {
        s1 += __shfl_xor_sync(0xffffffffu, s1, m);
        s2 += __shfl_xor_sync(0xffffffffu, s2, m);
    }
    if (lane == 0) { g_s1[row] = s1; g_s2[row] = s2; }
}

// ---------------- K3: fused masked-softmax @ h (split over 4 j-quarters) ----
// CTA = 64 rows x 2048 j, 128 threads. Thread tile: 8 rows (ty+8rr) x 8 cols
// (4tx.., 64+4tx..). Ws stored PLAIN; (w,w) packs built in registers (ALU) —
// per 2-j step: 32 smem wavefronts vs 64 fma2 -> 1:1 crossbar:fma balance.
// grid = 4 x 128 = 512 CTAs of 4 warps -> ~3.5 CTAs/SM (regs 128: 4x128x128 =
// 64K = full regfile), ~14 warps/SM: restores latency hiding lost in R16.
// Single pass over j (no max-subtract: exp args bounded ~[-5,+12]; masked
// entries contribute exactly 0).
__global__ __launch_bounds__(128, 4) void k_attn(const int* __restrict__ adj) {
    __shared__ float Ws[64][32];       // 8 KB, plain weights
    __shared__ float Hs[32][OUTF];     // 16 KB
    __shared__ float l_s[64];

    int tid = threadIdx.x;
    int tx = tid & 15, ty = tid >> 4;  // tx: f-group (8 cols), ty: row base (0..7)
    int quarter = blockIdx.x;          // 0..3: j-quarter
    int i0 = blockIdx.y * 64;
    int jbase = quarter * (NN / NSPLIT);

    // w-build mapping: 4 rows per thread (r_w + 16k), 4 cols c0..c0+3
    int r_w = tid >> 3;                // 0..15
    int c0  = (tid & 7) << 2;
    float s1v0 = g_s1[i0 + r_w];
    float s1v1 = g_s1[i0 + r_w + 16];
    float s1v2 = g_s1[i0 + r_w + 32];
    float s1v3 = g_s1[i0 + r_w + 48];

    u64 acc[8][4];                     // [row rr][lo.x lo.y hi.x hi.y]
#pragma unroll
    for (int r = 0; r < 8; r++)
#pragma unroll
        for (int c = 0; c < 4; c++) acc[r][c] = 0ULL;
    float lp0 = 0.f, lp1 = 0.f, lp2 = 0.f, lp3 = 0.f;

    const int NT = (NN / NSPLIT) / 32; // 64 tiles per quarter
    for (int t = 0; t < NT; t++) {
        int j0 = jbase + 32 * t;
        __syncthreads();               // previous tile's accumulate done

        // ---- build w tile (mask + leakyrelu + exp), store PLAIN ----
        float4 s2v = *(const float4*)&g_s2[j0 + c0];
        {
            int4 av = *(const int4*)&adj[(size_t)(i0 + r_w) * NN + j0 + c0];
            float e, w0, w1, w2, w3;
            e = s1v0 + s2v.x; e = e > 0.f ? e : 0.2f * e; w0 = av.x > 0 ? __expf(e) : 0.f;
            e = s1v0 + s2v.y; e = e > 0.f ? e : 0.2f * e; w1 = av.y > 0 ? __expf(e) : 0.f;
            e = s1v0 + s2v.z; e = e > 0.f ? e : 0.2f * e; w2 = av.z > 0 ? __expf(e) : 0.f;
            e = s1v0 + s2v.w; e = e > 0.f ? e : 0.2f * e; w3 = av.w > 0 ? __expf(e) : 0.f;
            lp0 += (w0 + w1) + (w2 + w3);
            *(float4*)&Ws[r_w][c0] = make_float4(w0, w1, w2, w3);
        }
        {
            int4 av = *(const int4*)&adj[(size_t)(i0 + r_w + 16) * NN + j0 + c0];
            float e, w0, w1, w2, w3;
            e = s1v1 + s2v.x; e = e > 0.f ? e : 0.2f * e; w0 = av.x > 0 ? __expf(e) : 0.f;
            e = s1v1 + s2v.y; e = e > 0.f ? e : 0.2f * e; w1 = av.y > 0 ? __expf(e) : 0.f;
            e = s1v1 + s2v.z; e = e > 0.f ? e : 0.2f * e; w2 = av.z > 0 ? __expf(e) : 0.f;
            e = s1v1 + s2v.w; e = e > 0.f ? e : 0.2f * e; w3 = av.w > 0 ? __expf(e) : 0.f;
            lp1 += (w0 + w1) + (w2 + w3);
            *(float4*)&Ws[r_w + 16][c0] = make_float4(w0, w1, w2, w3);
        }
        {
            int4 av = *(const int4*)&adj[(size_t)(i0 + r_w + 32) * NN + j0 + c0];
            float e, w0, w1, w2, w3;
            e = s1v2 + s2v.x; e = e > 0.f ? e : 0.2f * e; w0 = av.x > 0 ? __expf(e) : 0.f;
            e = s1v2 + s2v.y; e = e > 0.f ? e : 0.2f * e; w1 = av.y > 0 ? __expf(e) : 0.f;
            e = s1v2 + s2v.z; e = e > 0.f ? e : 0.2f * e; w2 = av.z > 0 ? __expf(e) : 0.f;
            e = s1v2 + s2v.w; e = e > 0.f ? e : 0.2f * e; w3 = av.w > 0 ? __expf(e) : 0.f;
            lp2 += (w0 + w1) + (w2 + w3);
            *(float4*)&Ws[r_w + 32][c0] = make_float4(w0, w1, w2, w3);
        }
        {
            int4 av = *(const int4*)&adj[(size_t)(i0 + r_w + 48) * NN + j0 + c0];
            float e, w0, w1, w2, w3;
            e = s1v3 + s2v.x; e = e > 0.f ? e : 0.2f * e; w0 = av.x > 0 ? __expf(e) : 0.f;
            e = s1v3 + s2v.y; e = e > 0.f ? e : 0.2f * e; w1 = av.y > 0 ? __expf(e) : 0.f;
            e = s1v3 + s2v.z; e = e > 0.f ? e : 0.2f * e; w2 = av.z > 0 ? __expf(e) : 0.f;
            e = s1v3 + s2v.w; e = e > 0.f ? e : 0.2f * e; w3 = av.w > 0 ? __expf(e) : 0.f;
            lp3 += (w0 + w1) + (w2 + w3);
            *(float4*)&Ws[r_w + 48][c0] = make_float4(w0, w1, w2, w3);
        }

        // ---- stage h tile (32 rows x 128 f = 1024 float4 / 128 thr) ----
#pragma unroll
        for (int q = 0; q < 8; q++) {
            int p = tid + 128 * q;
            int hr = p >> 5, hc = (p & 31) << 2;
            *(float4*)&Hs[hr][hc] = *(const float4*)&g_h[(size_t)(j0 + hr) * OUTF + hc];
        }
        __syncthreads();

        // ---- accumulate: per 2-j: 4 LDS.128 + 8 LDS.64 (32 wf) / 64 fma2 ----
#pragma unroll 2
        for (int jp = 0; jp < 16; jp++) {
            int jj = 2 * jp;
            ulonglong2 h0a = *(const ulonglong2*)&Hs[jj][4 * tx];
            ulonglong2 h0b = *(const ulonglong2*)&Hs[jj][64 + 4 * tx];
            ulonglong2 h1a = *(const ulonglong2*)&Hs[jj + 1][4 * tx];
            ulonglong2 h1b = *(const ulonglong2*)&Hs[jj + 1][64 + 4 * tx];
#pragma unroll
            for (int rr = 0; rr < 8; rr++) {
                float2 wv = *(const float2*)&Ws[ty + 8 * rr][jj];
                u64 w0 = pack2(wv.x, wv.x);
                u64 w1 = pack2(wv.y, wv.y);
                acc[rr][0] = fma2(w0, h0a.x, acc[rr][0]);
                acc[rr][1] = fma2(w0, h0a.y, acc[rr][1]);
                acc[rr][2] = fma2(w0, h0b.x, acc[rr][2]);
                acc[rr][3] = fma2(w0, h0b.y, acc[rr][3]);
                acc[rr][0] = fma2(w1, h1a.x, acc[rr][0]);
                acc[rr][1] = fma2(w1, h1a.y, acc[rr][1]);
                acc[rr][2] = fma2(w1, h1b.x, acc[rr][2]);
                acc[rr][3] = fma2(w1, h1b.y, acc[rr][3]);
            }
        }
    }

    // ---- finalize: partial row sums (reduce over 8 col-threads) ----
#pragma unroll
    for (int m = 1; m < 8; m <<= 1) {
        lp0 += __shfl_xor_sync(0xffffffffu, lp0, m);
        lp1 += __shfl_xor_sync(0xffffffffu, lp1, m);
        lp2 += __shfl_xor_sync(0xffffffffu, lp2, m);
        lp3 += __shfl_xor_sync(0xffffffffu, lp3, m);
    }
    __syncthreads();
    if ((tid & 7) == 0) {
        l_s[r_w]      = lp0;
        l_s[r_w + 16] = lp1;
        l_s[r_w + 32] = lp2;
        l_s[r_w + 48] = lp3;
    }
    __syncthreads();
    if (tid < 64) g_l[quarter][i0 + tid] = l_s[tid];

    // ---- write unnormalized partial acc ----
#pragma unroll
    for (int rr = 0; rr < 8; rr++) {
        int row = ty + 8 * rr;
        float x0, x1, x2, x3;
        unpack2(acc[rr][0], x0, x1);
        unpack2(acc[rr][1], x2, x3);
        *(float4*)&g_hpp[quarter][(size_t)(i0 + row) * OUTF + 4 * tx] =
            make_float4(x0, x1, x2, x3);
        unpack2(acc[rr][2], x0, x1);
        unpack2(acc[rr][3], x2, x3);
        *(float4*)&g_hpp[quarter][(size_t)(i0 + row) * OUTF + 64 + 4 * tx] =
            make_float4(x0, x1, x2, x3);
    }
}

// ---------------- K3b: combine j-quarters: hp = sum(p)/sum(l) ---------------
__global__ __launch_bounds__(256) void k_comb() {
    int idx = blockIdx.x * 256 + threadIdx.x;       // over NN*OUTF
    int row = idx >> 7;
    float inv = 1.0f / (g_l[0][row] + g_l[1][row] + g_l[2][row] + g_l[3][row]);
    g_hp[idx] = (g_hpp[0][idx] + g_hpp[1][idx] + g_hpp[2][idx] + g_hpp[3][idx]) * inv;
}

// ---------------- K4/K5: BatchNorm stats (deterministic tree) ---------------
__global__ __launch_bounds__(256) void k_bn1() {
    int f = threadIdx.x & 127, half = threadIdx.x >> 7;
    int b = blockIdx.x;
    float s = 0.f, q = 0.f;
    for (int k = 0; k < 64; k++) {
        float v = g_hp[(size_t)(b * 128 + half + 2 * k) * OUTF + f];
        s += v; q += v * v;
    }
    __shared__ float ss[2][128], qs[2][128];
    ss[half][f] = s; qs[half][f] = q;
    __syncthreads();
    if (threadIdx.x < 128) {
        g_part[b * OUTF + f]              = ss[0][f] + ss[1][f];
        g_part[64 * OUTF + b * OUTF + f]  = qs[0][f] + qs[1][f];
    }
}

__global__ void k_bn2() {
    int f = threadIdx.x;  // 128 threads
    float S = 0.f, Q = 0.f;
    for (int b = 0; b < 64; b++) {
        S += g_part[b * OUTF + f];
        Q += g_part[64 * OUTF + b * OUTF + f];
    }
    float mean = S * (1.0f / NN);
    float var  = Q * (1.0f / NN) - mean * mean;
    g_mean[f] = mean;
    g_rstd[f] = rsqrtf(var + 1e-5f);
}

// ---------------- K6: normalize + ELU ---------------------------------------
__global__ __launch_bounds__(256) void k_out(const float* __restrict__ gamma,
                                             const float* __restrict__ beta,
                                             float* __restrict__ out) {
    int idx = blockIdx.x * 256 + threadIdx.x;
    int f = idx & 127;
    float v = (g_hp[idx] - g_mean[f]) * g_rstd[f] * gamma[f] + beta[f];
    out[idx] = v > 0.f ? v : expm1f(v);
}

// ---------------- launch -----------------------------------------------------
extern "C" void kernel_launch(void* const* d_in, const int* in_sizes, int n_in,
                              void* d_out, int out_size) {
    const float* inp   = (const float*)d_in[0];   // 8192x512
    const int*   adj   = (const int*)d_in[1];     // 8192x8192
    const float* W     = (const float*)d_in[2];   // 128x128
    const float* a     = (const float*)d_in[3];   // 256
    const float* gamma = (const float*)d_in[4];   // 128
    const float* beta  = (const float*)d_in[5];   // 128
    float* out = (float*)d_out;                   // 8192x128

    k_ham <<<512, 128>>>(W);
    k_h   <<<dim3(2, 128), 256>>>(inp);
    k_s   <<<1024, 256>>>(a);
    k_attn<<<dim3(NSPLIT, 128), 128>>>(adj);
    k_comb<<<4096, 256>>>();
    k_bn1 <<<64, 256>>>();
    k_bn2 <<<1, 128>>>();
    k_out <<<4096, 256>>>(gamma, beta, out);
}